// round 2
// baseline (speedup 1.0000x reference)
#include <cuda_runtime.h>
#include <math.h>

// ISTFT: B=32, C=2 -> BC=64 channels; F=513 bins; T=1024 frames; n_fft=1024; hop=256.
// Per frame: irfft(1024) via half-size 512-pt complex inverse FFT (radix-8 Stockham,
// 3 stages in smem), Hann window, overlap-add into smem accumulator, crop 512, /2.

#define FRAMES_PER_CTA 16
#define GROUPS 4
#define ACC_LEN 4864      // 256*15 + 1024
#define ACC_F2  2432
#define INT_LO 768        // interior (exclusively owned) region of acc
#define INT_HI 4096
#define OUT_PER_BC 262400

__device__ __forceinline__ float2 cmul(float2 a, float2 b) {
    return make_float2(a.x * b.x - a.y * b.y, a.x * b.y + a.y * b.x);
}
__device__ __forceinline__ float2 cadd(float2 a, float2 b) { return make_float2(a.x + b.x, a.y + b.y); }
__device__ __forceinline__ float2 csub(float2 a, float2 b) { return make_float2(a.x - b.x, a.y - b.y); }
__device__ __forceinline__ float2 cmuli(float2 a) { return make_float2(-a.y, a.x); }  // * i

__device__ __forceinline__ int P(int i) { return i + (i >> 3); }  // smem pad swizzle

// radix-8 inverse butterfly: b[u] = sum_t a[t] * e^{+2*pi*i*t*u/8}
__device__ __forceinline__ void bfly8(const float2* a, float2* b) {
    const float r = 0.70710678118654752f;
    float2 p0 = cadd(a[0], a[4]), p1 = csub(a[0], a[4]);
    float2 p2 = cadd(a[2], a[6]), p3 = cmuli(csub(a[2], a[6]));
    float2 e0 = cadd(p0, p2), e2 = csub(p0, p2), e1 = cadd(p1, p3), e3 = csub(p1, p3);
    float2 q0 = cadd(a[1], a[5]), q1 = csub(a[1], a[5]);
    float2 q2 = cadd(a[3], a[7]), q3 = cmuli(csub(a[3], a[7]));
    float2 o0 = cadd(q0, q2), o2 = csub(q0, q2), o1 = cadd(q1, q3), o3 = csub(q1, q3);
    b[0] = cadd(e0, o0); b[4] = csub(e0, o0);
    float2 w1 = make_float2(r, r), w3 = make_float2(-r, r);
    float2 t1 = cmul(o1, w1); b[1] = cadd(e1, t1); b[5] = csub(e1, t1);
    float2 t2 = cmuli(o2);    b[2] = cadd(e2, t2); b[6] = csub(e2, t2);
    float2 t3 = cmul(o3, w3); b[3] = cadd(e3, t3); b[7] = csub(e3, t3);
}

__global__ void __launch_bounds__(256) istft_kernel(const float2* __restrict__ in,
                                                    float* __restrict__ out) {
    __shared__ float2 buf[4][577];     // per-frame FFT workspace (padded 512 + swizzle room)
    __shared__ float2 acc2[ACC_F2];    // overlap-add accumulator (4864 floats)
    __shared__ float2 tw512[512];      // e^{+2pi i k/512}
    __shared__ float2 tw1024[513];     // e^{+2pi i k/1024} (pack twiddles + hann via .x)
    __shared__ float  nyq[4];          // Re(X[512]) per frame in group

    const int tid = threadIdx.x;
    const int bc = blockIdx.y;
    const int tbase = blockIdx.x * FRAMES_PER_CTA;

    // ---- init tables + accumulator ----
    for (int i = tid; i < 512; i += 256) {
        float s, c;
        sincosf((float)(6.283185307179586 * i / 512.0), &s, &c);
        tw512[i] = make_float2(c, s);
    }
    for (int i = tid; i < 513; i += 256) {
        float s, c;
        sincosf((float)(6.283185307179586 * i / 1024.0), &s, &c);
        tw1024[i] = make_float2(c, s);
    }
    for (int i = tid; i < ACC_F2; i += 256) acc2[i] = make_float2(0.f, 0.f);
    __syncthreads();

    const int jf = tid >> 6;   // frame within group of 4
    const int lt = tid & 63;   // lane within frame's 64-thread FFT team
    const int jj = lt >> 3, kk = lt & 7;

    for (int g = 0; g < GROUPS; g++) {
        // ---- load spectra for frames tbase+4g+{0..3} (coalesced 32B per bin) ----
        {
            const int t0 = tbase + 4 * g;
            const float2* base = in + (size_t)bc * 513 * 1024 + t0;
            for (int idx = tid; idx < 513 * 4; idx += 256) {
                int f = idx >> 2, j = idx & 3;
                float2 v = base[(size_t)f * 1024 + j];
                if (f < 512) buf[j][P(f)] = v;
                else nyq[j] = v.x;   // Im(X[512]) ignored (c2r semantics)
            }
        }
        __syncthreads();

        float2 a[8], b[8];

        // ---- pack C[k] (C2R -> half-size C2C) fused with Stockham stage 0 ----
        #pragma unroll
        for (int r_ = 0; r_ < 8; r_++) {
            int k = lt + (r_ << 6);
            if (k == 0) {
                float x0r = buf[jf][P(0)].x;  // Im(X[0]) ignored (c2r semantics)
                float ny = nyq[jf];
                a[0] = make_float2((x0r + ny) * 0.015625f, (x0r - ny) * 0.015625f);
            } else {
                float2 X  = buf[jf][P(k)];
                float2 Xc = buf[jf][P(512 - k)];
                float2 A  = make_float2(X.x + Xc.x, X.y - Xc.y);   // X[k] + conj(X[512-k])
                float2 D  = make_float2(X.x - Xc.x, X.y + Xc.y);   // X[k] - conj(X[512-k])
                float2 wD = cmul(tw1024[k], D);
                // C = (A + i*w*D) / 64   (1/2 pack * 1/512 ifft * sqrt(1024) * 1/2 coeff)
                a[r_] = make_float2((A.x - wD.y) * 0.015625f, (A.y + wD.x) * 0.015625f);
            }
        }
        __syncthreads();                 // all reads done before in-place writes
        bfly8(a, b);                     // stage 0: l=1, no twiddles
        #pragma unroll
        for (int u = 0; u < 8; u++) buf[jf][P(lt + (u << 6))] = b[u];
        __syncthreads();

        // ---- stage 1: l=8 ----
        #pragma unroll
        for (int t = 0; t < 8; t++) a[t] = buf[jf][P(kk + 64 * jj + 8 * t)];
        __syncthreads();
        #pragma unroll
        for (int t = 1; t < 8; t++) a[t] = cmul(a[t], tw512[(8 * jj * t) & 511]);
        bfly8(a, b);
        #pragma unroll
        for (int u = 0; u < 8; u++) buf[jf][P(kk + 8 * jj + 64 * u)] = b[u];
        __syncthreads();

        // ---- stage 2: l=64, then window + overlap-add ----
        #pragma unroll
        for (int t = 0; t < 8; t++) a[t] = buf[jf][P(8 * lt + t)];
        #pragma unroll
        for (int t = 1; t < 8; t++) a[t] = cmul(a[t], tw512[(lt * t) & 511]);
        bfly8(a, b);   // b[u] = z[lt + 64u]; samples 2m (Re), 2m+1 (Im)

        // 4-round Latin-square schedule: frame jf writes chunk c=(r+2*jf)&3 each round;
        // occupied acc regions jf+c are distinct per round -> race-free overlap-add.
        const int offh = ((g << 2) + jf) << 7;   // 256*(4g+jf) in float2 units
        #pragma unroll
        for (int rr = 0; rr < 4; rr++) {
            int c = (rr + 2 * jf) & 3;
            #pragma unroll
            for (int h = 0; h < 2; h++) {
                int u = 2 * c + h;
                int m = lt + (u << 6);
                int s = 2 * m;
                int i0 = (s <= 512) ? s : 1024 - s;
                int i1 = (s + 1 <= 512) ? (s + 1) : 1024 - (s + 1);
                float h0 = 0.5f - 0.5f * tw1024[i0].x;   // hann(s)
                float h1 = 0.5f - 0.5f * tw1024[i1].x;   // hann(s+1)
                float2 v = acc2[offh + m];
                v.x += h0 * b[u].x;
                v.y += h1 * b[u].y;
                acc2[offh + m] = v;
            }
            __syncthreads();
        }
    }

    // ---- writeout: interior exclusively owned -> plain store; edges -> atomicAdd ----
    const float* accf = (const float*)acc2;
    float* obase = out + (size_t)bc * OUT_PER_BC;
    const int q0 = tbase << 8;   // 256 * tbase
    for (int idx = tid; idx < ACC_LEN; idx += 256) {
        int q = q0 + idx;
        if (q < 512) continue;               // crop y[:, :512]
        float v = accf[idx];
        int p = q - 512;
        if (idx >= INT_LO && idx < INT_HI) obase[p] = v;
        else atomicAdd(&obase[p], v);
    }
}

extern "C" void kernel_launch(void* const* d_in, const int* in_sizes, int n_in,
                              void* d_out, int out_size) {
    const float2* in = (const float2*)d_in[0];
    float* out = (float*)d_out;
    // zero output (edge atomics require it; interior is overwritten by plain stores)
    cudaMemsetAsync(d_out, 0, (size_t)out_size * sizeof(float), 0);
    dim3 grid(1024 / FRAMES_PER_CTA, 64);   // (t-groups, bc)
    istft_kernel<<<grid, 256>>>(in, out);
}

// round 3
// speedup vs baseline: 1.5936x; 1.5936x over previous
#include <cuda_runtime.h>
#include <math.h>

// ISTFT: BC=64 channels; F=513 bins; T=1024 frames; n_fft=1024; hop=256.
// irfft(1024) per frame via half-size 512-pt complex inverse FFT (radix-8
// Stockham, 3 stages in smem), Hann window (register-rotated), overlap-add
// into smem accumulator (store-then-add schedule), crop 512, /2.

#define FRAMES_PER_CTA 16
#define GROUPS 4
#define ACC_LEN 4864      // 256*15 + 1024 floats
#define ACC_F2  2432
#define INT_LO 768        // interior (exclusively owned) region of acc, floats
#define INT_HI 4096
#define OUT_PER_BC 262400
#define BUFS 580          // buf row stride (f2): >=575 and ==4 (mod 16) for bank spread

__device__ __forceinline__ float2 cmul(float2 a, float2 b) {
    return make_float2(a.x * b.x - a.y * b.y, a.x * b.y + a.y * b.x);
}
__device__ __forceinline__ float2 cadd(float2 a, float2 b) { return make_float2(a.x + b.x, a.y + b.y); }
__device__ __forceinline__ float2 csub(float2 a, float2 b) { return make_float2(a.x - b.x, a.y - b.y); }
__device__ __forceinline__ float2 cmuli(float2 a) { return make_float2(-a.y, a.x); }  // * i

__device__ __forceinline__ int P(int i) { return i + (i >> 3); }  // smem pad swizzle

// radix-8 inverse butterfly: b[u] = sum_t a[t] * e^{+2*pi*i*t*u/8}
__device__ __forceinline__ void bfly8(const float2* a, float2* b) {
    const float r = 0.70710678118654752f;
    float2 p0 = cadd(a[0], a[4]), p1 = csub(a[0], a[4]);
    float2 p2 = cadd(a[2], a[6]), p3 = cmuli(csub(a[2], a[6]));
    float2 e0 = cadd(p0, p2), e2 = csub(p0, p2), e1 = cadd(p1, p3), e3 = csub(p1, p3);
    float2 q0 = cadd(a[1], a[5]), q1 = csub(a[1], a[5]);
    float2 q2 = cadd(a[3], a[7]), q3 = cmuli(csub(a[3], a[7]));
    float2 o0 = cadd(q0, q2), o2 = csub(q0, q2), o1 = cadd(q1, q3), o3 = csub(q1, q3);
    b[0] = cadd(e0, o0); b[4] = csub(e0, o0);
    float2 w1 = make_float2(r, r), w3 = make_float2(-r, r);
    float2 t1 = cmul(o1, w1); b[1] = cadd(e1, t1); b[5] = csub(e1, t1);
    float2 t2 = cmuli(o2);    b[2] = cadd(e2, t2); b[6] = csub(e2, t2);
    float2 t3 = cmul(o3, w3); b[3] = cadd(e3, t3); b[7] = csub(e3, t3);
}

__global__ void __launch_bounds__(256) istft_kernel(const float2* __restrict__ in,
                                                    float* __restrict__ out) {
    __shared__ float2 buf[4][BUFS];    // per-frame FFT workspace
    __shared__ float2 acc2[ACC_F2];    // overlap-add accumulator
    __shared__ float2 tw512[512];      // e^{+2pi i k/512}
    __shared__ float2 tw1024[513];     // e^{+2pi i k/1024}

    const int tid = threadIdx.x;
    const int bc = blockIdx.y;
    const int tbase = blockIdx.x * FRAMES_PER_CTA;

    // ---- init tables; zero only the never-stored edge chunks (f2 [0,384)) ----
    for (int i = tid; i < 512; i += 256) {
        float s, c;
        sincosf((float)(6.283185307179586 * i / 512.0), &s, &c);
        tw512[i] = make_float2(c, s);
    }
    for (int i = tid; i < 513; i += 256) {
        float s, c;
        sincosf((float)(6.283185307179586 * i / 1024.0), &s, &c);
        tw1024[i] = make_float2(c, s);
    }
    for (int i = tid; i < 384; i += 256) acc2[i] = make_float2(0.f, 0.f);
    __syncthreads();

    const int jf = tid >> 6;   // frame within group of 4
    const int lt = tid & 63;   // lane within frame's 64-thread FFT team
    const int jj = lt >> 3, kk = lt & 7;
    const float SC = 0.015625f;   // 1/64: 1/2 pack * 1/512 ifft * sqrt(1024) * 1/2 coeff

    for (int g = 0; g < GROUPS; g++) {
        // ---- load spectra + C2R pack fused (each bin read once, coalesced) ----
        {
            const int t0 = tbase + 4 * g;
            const float2* base = in + (size_t)bc * 513 * 1024 + t0;
            for (int idx = tid; idx < 257 * 4; idx += 256) {
                int f = idx >> 2, j = idx & 3;
                float2 X = base[(size_t)f * 1024 + j];
                float2 Y = base[(size_t)(512 - f) * 1024 + j];
                if (f == 0) { X.y = 0.f; Y.y = 0.f; }   // c2r: Im(X[0]), Im(X[512]) ignored
                float2 w = tw1024[f];
                float2 A = make_float2(X.x + Y.x, X.y - Y.y);   // X[f] + conj(X[512-f])
                float2 D = make_float2(X.x - Y.x, X.y + Y.y);   // X[f] - conj(X[512-f])
                float2 wD = cmul(w, D);
                buf[j][P(f)] = make_float2((A.x - wD.y) * SC, (A.y + wD.x) * SC);
                if (f > 0 && f < 256)   // partner C[512-f] from same registers (w' = -conj w)
                    buf[j][P(512 - f)] = make_float2((A.x + wD.y) * SC, (-A.y + wD.x) * SC);
            }
        }
        __syncthreads();

        float2 a[8], b[8];

        // ---- stage 0: l=1, no twiddles ----
        #pragma unroll
        for (int r_ = 0; r_ < 8; r_++) a[r_] = buf[jf][P(lt + (r_ << 6))];
        __syncthreads();
        bfly8(a, b);
        #pragma unroll
        for (int u = 0; u < 8; u++) buf[jf][P(lt + (u << 6))] = b[u];
        __syncthreads();

        // ---- stage 1: l=8, twiddles by register rotation from tw512[8*jj] ----
        #pragma unroll
        for (int t = 0; t < 8; t++) a[t] = buf[jf][P(kk + 64 * jj + 8 * t)];
        __syncthreads();
        {
            float2 w = tw512[8 * jj];
            float2 cw = w;
            a[1] = cmul(a[1], cw);
            #pragma unroll
            for (int t = 2; t < 8; t++) { cw = cmul(cw, w); a[t] = cmul(a[t], cw); }
        }
        bfly8(a, b);
        #pragma unroll
        for (int u = 0; u < 8; u++) buf[jf][P(kk + 8 * jj + 64 * u)] = b[u];
        __syncthreads();

        // ---- stage 2: l=64, twiddles from tw512[lt]; then window in registers ----
        #pragma unroll
        for (int t = 0; t < 8; t++) a[t] = buf[jf][P(8 * lt + t)];
        {
            float2 w = tw512[lt];
            float2 cw = w;
            a[1] = cmul(a[1], cw);
            #pragma unroll
            for (int t = 2; t < 8; t++) { cw = cmul(cw, w); a[t] = cmul(a[t], cw); }
        }
        bfly8(a, b);   // b[u] = z[lt + 64u]; even sample in .x, odd in .y

        // Hann window: h(s) = 0.5 - 0.5 cos(2 pi s / 1024); s = 2m (.x), 2m+1 (.y),
        // m = lt + 64u. Base angles from table, advance u by pi/4 rotation.
        {
            const float R = 0.70710678118654752f;
            float2 e = tw1024[2 * lt];
            float2 o = tw1024[2 * lt + 1];
            #pragma unroll
            for (int u = 0; u < 8; u++) {
                b[u].x *= (0.5f - 0.5f * e.x);
                b[u].y *= (0.5f - 0.5f * o.x);
                float ex = (e.x - e.y) * R, ey = (e.x + e.y) * R; e = make_float2(ex, ey);
                float ox = (o.x - o.y) * R, oy = (o.x + o.y) * R; o = make_float2(ox, oy);
            }
        }

        // ---- OLA: chunk c=3 is first-touched by this frame -> plain store;
        //      then chunks 0,1,2 add. Fixed-c rounds are race-free (regions jf+c
        //      distinct across jf). All indices compile-time. ----
        const int offh = ((g << 2) + jf) << 7;   // 128*(4g+jf) in f2 units
        {
            int m6 = lt + (6 << 6), m7 = lt + (7 << 6);
            acc2[offh + m6] = b[6];
            acc2[offh + m7] = b[7];
        }
        __syncthreads();
        #pragma unroll
        for (int c = 0; c < 3; c++) {
            #pragma unroll
            for (int h = 0; h < 2; h++) {
                int u = 2 * c + h;
                int m = lt + (u << 6);
                float2 v = acc2[offh + m];
                v.x += b[u].x; v.y += b[u].y;
                acc2[offh + m] = v;
            }
            __syncthreads();
        }
    }

    // ---- writeout: interior exclusively owned -> plain store; edges -> atomicAdd ----
    const float* accf = (const float*)acc2;
    float* obase = out + (size_t)bc * OUT_PER_BC;
    const int q0 = tbase << 8;   // 256 * tbase
    for (int idx = tid; idx < ACC_LEN; idx += 256) {
        int q = q0 + idx;
        if (q < 512) continue;               // crop y[:, :512]
        float v = accf[idx];
        int p = q - 512;
        if (idx >= INT_LO && idx < INT_HI) obase[p] = v;
        else atomicAdd(&obase[p], v);
    }
}

extern "C" void kernel_launch(void* const* d_in, const int* in_sizes, int n_in,
                              void* d_out, int out_size) {
    const float2* in = (const float2*)d_in[0];
    float* out = (float*)d_out;
    // zero output (edge atomics require it; interior is overwritten by plain stores)
    cudaMemsetAsync(d_out, 0, (size_t)out_size * sizeof(float), 0);
    dim3 grid(1024 / FRAMES_PER_CTA, 64);   // (t-groups, bc)
    istft_kernel<<<grid, 256>>>(in, out);
}